// round 16
// baseline (speedup 1.0000x reference)
#include <cuda_runtime.h>
#include <cuda_fp16.h>
#include <cstdint>

#define N_NODES 50000
#define NPAD 50048          // 391 * 128 — padded row count, no bounds checks in GEMM
#define N_EDGES 800000
#define D 128
#define NW2 64              // uint32 words per plain-fp16 row (256 B)
#define N_GRAPHS 128
#define OUT_DIM 16
#define SLOTS 64            // fixed adjacency slots per node (Poisson(16), P(>64)~1e-20)
#define STRA 136            // fp16 row stride for MMA tiles (272B: conflict-free ldmatrix)
#define IMG (128 * STRA)    // fp16 elems per 128x128 W image (34816 B)
#define NT 391              // 128-row tiles covering NPAD
#define GRID_GEMM 148       // persistent CTAs
#define GT 256              // GEMM threads (8 warps, warp tile 64m x 32n)

// ---------------------------------------------------------------------------
// Scratch.  Features: plain fp16 rows, 64 words (256 B) each, padded to NPAD.
// ---------------------------------------------------------------------------
__device__ uint32_t g_xs[NPAD * NW2];
__device__ uint32_t g_aggs[NPAD * NW2];
__device__ uint32_t g_h1[NPAD * NW2];
__device__ uint32_t g_h2[NPAD * NW2];
__device__ float g_sums[N_GRAPHS * D];
__device__ float g_cnt[N_GRAPHS];
__device__ int g_deg[N_NODES];
__device__ int g_adj[N_NODES * SLOTS];
__device__ __align__(16) __half g_Wf16[3 * 2 * IMG];   // per layer: [rel][root]

// ---------------------------------------------------------------------------
// Helpers
// ---------------------------------------------------------------------------
__device__ __forceinline__ uint32_t smem_u32(const void* p) {
    uint32_t a;
    asm("{ .reg .u64 t; cvta.to.shared.u64 t, %1; cvt.u32.u64 %0, t; }"
        : "=r"(a) : "l"(p));
    return a;
}
__device__ __forceinline__ float2 up2(uint32_t w) {    // packed fp16x2 -> f32x2
    float2 f;
    asm("{ .reg .f16 h0, h1; mov.b32 {h0, h1}, %2;\n\t"
        "  cvt.f32.f16 %0, h0; cvt.f32.f16 %1, h1; }"
        : "=f"(f.x), "=f"(f.y) : "r"(w));
    return f;
}
__device__ __forceinline__ uint32_t packh2(float a, float b) {  // a->lo, b->hi
    uint32_t r;
    asm("cvt.rn.f16x2.f32 %0, %1, %2;" : "=r"(r) : "f"(b), "f"(a));
    return r;
}
__device__ __forceinline__ uint32_t hadd2(uint32_t a, uint32_t b) {
    uint32_t r;
    asm("add.rn.f16x2 %0, %1, %2;" : "=r"(r) : "r"(a), "r"(b));
    return r;
}
__device__ __forceinline__ void ldsm4(uint32_t* r, uint32_t addr) {
    asm volatile("ldmatrix.sync.aligned.m8n8.x4.shared.b16 {%0,%1,%2,%3}, [%4];"
                 : "=r"(r[0]), "=r"(r[1]), "=r"(r[2]), "=r"(r[3]) : "r"(addr));
}
__device__ __forceinline__ void mma16816h(float* c, const uint32_t* a,
                                          uint32_t b0, uint32_t b1) {
    asm volatile(
        "mma.sync.aligned.m16n8k16.row.col.f32.f16.f16.f32 "
        "{%0,%1,%2,%3}, {%4,%5,%6,%7}, {%8,%9}, {%0,%1,%2,%3};"
        : "+f"(c[0]), "+f"(c[1]), "+f"(c[2]), "+f"(c[3])
        : "r"(a[0]), "r"(a[1]), "r"(a[2]), "r"(a[3]), "r"(b0), "r"(b1));
}
__device__ __forceinline__ void cp16(uint32_t d, const void* s) {
    asm volatile("cp.async.cg.shared.global [%0], [%1], 16;"
                 :: "r"(d), "l"(s) : "memory");
}
__device__ __forceinline__ void cp_commit() {
    asm volatile("cp.async.commit_group;" ::: "memory");
}
__device__ __forceinline__ void cp_wait0() {
    asm volatile("cp.async.wait_group 0;" ::: "memory");
}

// ---------------------------------------------------------------------------
// Setup: zero deg/pool, convert x -> plain fp16, transpose weights to fp16.
// Extra 6 blocks (past SETUP_BLOCKS) do the weight prep.
// ---------------------------------------------------------------------------
#define SETUP_BLOCKS 6250    // ceil(N_NODES*32 / 256)
__global__ void k_setup(const float* __restrict__ x,
                        const float* __restrict__ Wrel,
                        const float* __restrict__ Wroot) {
    if (blockIdx.x >= SETUP_BLOCKS) {
        int m = blockIdx.x - SETUP_BLOCKS;    // layer*2 + isroot
        const float* W = ((m & 1) ? Wroot : Wrel) + (m >> 1) * D * D;
        __half* dst = g_Wf16 + m * IMG;
        for (int i = threadIdx.x; i < D * D; i += 256) {
            int n = i & 127;
            int k = i >> 7;
            dst[n * STRA + k] = __float2half(W[k * D + n]);
        }
        return;
    }
    int i = blockIdx.x * blockDim.x + threadIdx.x;
    if (i < N_NODES) g_deg[i] = 0;
    if (i < N_GRAPHS * D) g_sums[i] = 0.f;
    if (i < N_GRAPHS) g_cnt[i] = 0.f;
    if (i < N_NODES * 32) {
        int node = i >> 5;
        int t4 = i & 31;
        float4 v = *reinterpret_cast<const float4*>(x + (size_t)node * D + t4 * 4);
        *reinterpret_cast<uint2*>(g_xs + (size_t)node * NW2 + t4 * 2) =
            make_uint2(packh2(v.x, v.y), packh2(v.z, v.w));
    }
    // Zero pad rows of all feature buffers (48 rows x 64 words = 1536 uint2 slots)
    if (i < (NPAD - N_NODES) * 32) {
        int node = N_NODES + (i >> 5);
        int t4 = i & 31;
        uint2 z = make_uint2(0u, 0u);
        *reinterpret_cast<uint2*>(g_xs + (size_t)node * NW2 + t4 * 2) = z;
        *reinterpret_cast<uint2*>(g_aggs + (size_t)node * NW2 + t4 * 2) = z;
        *reinterpret_cast<uint2*>(g_h1 + (size_t)node * NW2 + t4 * 2) = z;
        *reinterpret_cast<uint2*>(g_h2 + (size_t)node * NW2 + t4 * 2) = z;
    }
}

__global__ void k_fill(const int* __restrict__ ei) {
    int e = blockIdx.x * blockDim.x + threadIdx.x;
    if (e < N_EDGES) {
        int dst = ei[N_EDGES + e];
        int p = atomicAdd(&g_deg[dst], 1);
        if (p < SLOTS) g_adj[dst * SLOTS + p] = ei[e];
    }
}

// ---------------------------------------------------------------------------
// Gather: aggs[n] = fp16( sum_{s in adj(n)} h[s] ).
// TWO nodes per warp, 16 lanes/node, LDG.128 per lane per neighbor.
// One-level fp16 pair-summing (HADD2) before f32 accumulate.
// ---------------------------------------------------------------------------
__global__ __launch_bounds__(256) void k_gather(const uint32_t* __restrict__ h) {
    int gwarp = (blockIdx.x * blockDim.x + threadIdx.x) >> 5;
    int lane = threadIdx.x & 31;
    int n = gwarp * 2 + (lane >> 4);          // node for this half-warp
    if (n >= N_NODES) return;
    int hl = lane & 15;                       // half-lane: owns uint4 chunk hl
    int deg = g_deg[n];
    if (deg > SLOTS) deg = SLOTS;
    const int* adj = g_adj + n * SLOTS;
    float a0 = 0.f, a1 = 0.f, a2 = 0.f, a3 = 0.f;
    float a4 = 0.f, a5 = 0.f, a6 = 0.f, a7 = 0.f;

#define ACC_U4(u) do { \
        float2 f0 = up2((u).x), f1 = up2((u).y), f2 = up2((u).z), f3 = up2((u).w); \
        a0 += f0.x; a1 += f0.y; a2 += f1.x; a3 += f1.y; \
        a4 += f2.x; a5 += f2.y; a6 += f3.x; a7 += f3.y; } while (0)

    int i = 0;
    for (; i + 4 <= deg; i += 4) {
        int s0 = adj[i], s1 = adj[i + 1], s2 = adj[i + 2], s3 = adj[i + 3];
        uint4 u0 = *reinterpret_cast<const uint4*>(h + (size_t)s0 * NW2 + hl * 4);
        uint4 u1 = *reinterpret_cast<const uint4*>(h + (size_t)s1 * NW2 + hl * 4);
        uint4 u2 = *reinterpret_cast<const uint4*>(h + (size_t)s2 * NW2 + hl * 4);
        uint4 u3 = *reinterpret_cast<const uint4*>(h + (size_t)s3 * NW2 + hl * 4);
        uint4 p = make_uint4(hadd2(u0.x, u1.x), hadd2(u0.y, u1.y),
                             hadd2(u0.z, u1.z), hadd2(u0.w, u1.w));
        uint4 q = make_uint4(hadd2(u2.x, u3.x), hadd2(u2.y, u3.y),
                             hadd2(u2.z, u3.z), hadd2(u2.w, u3.w));
        ACC_U4(p);
        ACC_U4(q);
    }
    if (i + 2 <= deg) {
        int s0 = adj[i], s1 = adj[i + 1];
        uint4 u0 = *reinterpret_cast<const uint4*>(h + (size_t)s0 * NW2 + hl * 4);
        uint4 u1 = *reinterpret_cast<const uint4*>(h + (size_t)s1 * NW2 + hl * 4);
        uint4 p = make_uint4(hadd2(u0.x, u1.x), hadd2(u0.y, u1.y),
                             hadd2(u0.z, u1.z), hadd2(u0.w, u1.w));
        ACC_U4(p);
        i += 2;
    }
    if (i < deg) {
        int s = adj[i];
        uint4 u = *reinterpret_cast<const uint4*>(h + (size_t)s * NW2 + hl * 4);
        ACC_U4(u);
    }
#undef ACC_U4

    *reinterpret_cast<uint4*>(g_aggs + (size_t)n * NW2 + hl * 4) =
        make_uint4(packh2(a0, a1), packh2(a2, a3), packh2(a4, a5), packh2(a6, a7));
}

// ---------------------------------------------------------------------------
// Persistent HMMA GraphConv GEMM, weight fragments in REGISTERS:
//   hout = fp16( relu( agg@Wrel + hin@Wroot + b ) )
// 148 CTAs x 256 thr (8 warps, warp tile 64m x 32n), loop over 391 tiles.
// B frags (both images) loaded once per warp: 128 regs/thread, held all kernel.
// A tiles double-buffered via cp.async.  No weight smem in the hot loop.
// SMEM: bias 512 | buf0 {agg,h} 69632 | buf1 69632 = 139776 B
// ---------------------------------------------------------------------------
#define SMB_BUF0 512
#define SMB_BUF1 70144
#define SM_TOTAL 139776

// Issue cp.async for one 128-row tile pair (agg + hin) into a buffer.
__device__ __forceinline__ void issue_tile_copy(uint32_t sbase, uint32_t bufOff,
                                                const uint32_t* __restrict__ agg,
                                                const uint32_t* __restrict__ hin,
                                                int row0) {
    int tid = threadIdx.x;
#pragma unroll
    for (int it = 0; it < 8; it++) {
        int idx = it * GT + tid;
        int row = idx >> 4;                  // 16 uint4 per row
        int t4 = idx & 15;
        uint32_t so = bufOff + (uint32_t)((row * 68 + t4 * 4) * 4);
        cp16(sbase + so, agg + (size_t)(row0 + row) * NW2 + t4 * 4);
        cp16(sbase + so + 34816u, hin + (size_t)(row0 + row) * NW2 + t4 * 4);
    }
    cp_commit();
}

// Load this warp's B fragments for one W image from a staged smem copy.
__device__ __forceinline__ void load_bfrag(uint32_t stage, uint32_t (&bf)[8][2][4],
                                           int ncol0, int lane) {
    int bn = (lane & 7) + ((lane >> 4) & 1) * 8;
    int bkc = ((lane >> 3) & 1) * 8;
#pragma unroll
    for (int ks = 0; ks < 8; ks++)
#pragma unroll
        for (int np = 0; np < 2; np++) {
            uint32_t woff = (uint32_t)((ncol0 + np * 16 + bn) * (STRA * 2) +
                                       (ks * 16 + bkc) * 2);
            ldsm4(bf[ks][np], stage + woff);
        }
}

// One K=128 pass: c += A @ W, W fragments already in registers.
__device__ __forceinline__ void mma_pass_reg(float c[4][4][4], uint32_t aBase,
                                             const uint32_t (&bf)[8][2][4],
                                             int mrow0, int lane) {
    int arow = (lane & 7) + ((lane >> 3) & 1) * 8;
    int akc = ((lane >> 4) & 1) * 8;
#pragma unroll
    for (int ks = 0; ks < 8; ks++) {
        int k0 = ks * 16;
        uint32_t a[4][4];
#pragma unroll
        for (int mt = 0; mt < 4; mt++) {
            uint32_t off = (uint32_t)((mrow0 + mt * 16 + arow) * (STRA * 2) +
                                      (k0 + akc) * 2);
            ldsm4(a[mt], aBase + off);
        }
#pragma unroll
        for (int np = 0; np < 2; np++)
#pragma unroll
            for (int mt = 0; mt < 4; mt++) {
                mma16816h(c[mt][np * 2], a[mt], bf[ks][np][0], bf[ks][np][1]);
                mma16816h(c[mt][np * 2 + 1], a[mt], bf[ks][np][2], bf[ks][np][3]);
            }
    }
}

__global__ __launch_bounds__(GT, 1)
void k_gemm_mma(const uint32_t* __restrict__ hin,
                const __half* __restrict__ wlayer,   // [rel][root] images
                const float* __restrict__ bias,
                uint32_t* __restrict__ hout) {
    extern __shared__ char smem[];
    int tid = threadIdx.x;
    int w = tid >> 5;
    int lane = tid & 31;
    int mrow0 = (w & 1) * 64;        // 2 m-warps (4 x 16-row mt each)
    int ncol0 = (w >> 1) * 32;       // 4 n-warps
    uint32_t sbase = smem_u32(smem);

    if (tid < 128) ((float*)smem)[tid] = bias[tid];

    // Stage Wrel into buf0, snap fragments to registers; then Wroot.
    uint32_t bRel[8][2][4], bRoot[8][2][4];
    {
        const float4* s4 = reinterpret_cast<const float4*>(wlayer);
        float4* d4 = reinterpret_cast<float4*>(smem + SMB_BUF0);
#pragma unroll 2
        for (int i = tid; i < 2176; i += GT) d4[i] = s4[i];
        __syncthreads();
        load_bfrag(sbase + SMB_BUF0, bRel, ncol0, lane);
        __syncthreads();
#pragma unroll 2
        for (int i = tid; i < 2176; i += GT) d4[i] = s4[2176 + i];
        __syncthreads();
        load_bfrag(sbase + SMB_BUF0, bRoot, ncol0, lane);
        __syncthreads();
    }

    const float* sb = (const float*)smem;
    int g = lane >> 2;
    int t = lane & 3;
    const uint32_t bufOff[2] = {SMB_BUF0, SMB_BUF1};

    // Prologue: start copy of first tile into buf0
    int tile = blockIdx.x;
    issue_tile_copy(sbase, SMB_BUF0, g_aggs, hin, tile * 128);

    int cur = 0;
    while (tile < NT) {
        int next = tile + GRID_GEMM;
        cp_wait0();
        __syncthreads();                 // buf[cur] ready; all warps past prior reads
        if (next < NT)
            issue_tile_copy(sbase, bufOff[cur ^ 1], g_aggs, hin, next * 128);

        float c[4][4][4];
#pragma unroll
        for (int mt = 0; mt < 4; mt++)
#pragma unroll
            for (int nt = 0; nt < 4; nt++)
#pragma unroll
                for (int i = 0; i < 4; i++) c[mt][nt][i] = 0.f;

        mma_pass_reg(c, sbase + bufOff[cur], bRel, mrow0, lane);            // agg@Wrel
        mma_pass_reg(c, sbase + bufOff[cur] + 34816u, bRoot, mrow0, lane);  // hin@Wroot

        // Epilogue: bias + relu, write plain fp16 (rows padded; no guards)
        int row0 = tile * 128;
#pragma unroll
        for (int mt = 0; mt < 4; mt++) {
#pragma unroll
            for (int nt = 0; nt < 4; nt++) {
                int col = ncol0 + nt * 8 + t * 2;
                float b0 = sb[col], b1 = sb[col + 1];
                int r0 = row0 + mrow0 + mt * 16 + g;
                hout[(size_t)r0 * NW2 + (col >> 1)] =
                    packh2(fmaxf(c[mt][nt][0] + b0, 0.f),
                           fmaxf(c[mt][nt][1] + b1, 0.f));
                hout[(size_t)(r0 + 8) * NW2 + (col >> 1)] =
                    packh2(fmaxf(c[mt][nt][2] + b0, 0.f),
                           fmaxf(c[mt][nt][3] + b1, 0.f));
            }
        }
        tile = next;
        cur ^= 1;
    }
}

// ---------------------------------------------------------------------------
// Pool (reads plain fp16) + head
// ---------------------------------------------------------------------------
#define NODES_PER_WARP 4
__global__ __launch_bounds__(256) void k_pool(const uint32_t* __restrict__ h,
                                              const int* __restrict__ batch) {
    int gwarp = (blockIdx.x * blockDim.x + threadIdx.x) >> 5;
    int lane = threadIdx.x & 31;
#pragma unroll
    for (int i = 0; i < NODES_PER_WARP; i++) {
        int n = gwarp * NODES_PER_WARP + i;
        if (n >= N_NODES) return;
        int g = batch[n];
        uint2 u = *reinterpret_cast<const uint2*>(h + (size_t)n * NW2 + lane * 2);
        float2 f0 = up2(u.x), f1 = up2(u.y);
        float* dp = g_sums + g * D + lane * 4;
        asm volatile("red.global.add.v4.f32 [%0], {%1,%2,%3,%4};"
                     :: "l"(dp), "f"(f0.x), "f"(f0.y), "f"(f1.x), "f"(f1.y)
                     : "memory");
        if (lane == 0) atomicAdd(&g_cnt[g], 1.0f);
    }
}

__global__ __launch_bounds__(128) void k_head(const float* __restrict__ W1,
                                              const float* __restrict__ b1,
                                              const float* __restrict__ W2,
                                              const float* __restrict__ b2,
                                              float* __restrict__ out) {
    __shared__ float pooled[D];
    __shared__ float t[D];
    int g = blockIdx.x;
    int tid = threadIdx.x;
    float cnt = fmaxf(g_cnt[g], 1.0f);
    pooled[tid] = g_sums[g * D + tid] / cnt;
    __syncthreads();

    float acc = b1[tid];
#pragma unroll 8
    for (int k = 0; k < D; k++) acc += pooled[k] * W1[k * D + tid];
    t[tid] = acc;
    __syncthreads();

    if (tid < OUT_DIM) {
        float o = b2[tid];
#pragma unroll 8
        for (int k = 0; k < D; k++) o += t[k] * W2[k * OUT_DIM + tid];
        out[g * OUT_DIM + tid] = o;
    }
}

// ---------------------------------------------------------------------------
// Launch sequence (graph-capturable)
// ---------------------------------------------------------------------------
extern "C" void kernel_launch(void* const* d_in, const int* in_sizes, int n_in,
                              void* d_out, int out_size) {
    const float* x = (const float*)d_in[0];
    const int* ei = (const int*)d_in[1];      // int32 (JAX x64 disabled)
    const int* batch = (const int*)d_in[2];   // int32
    const float* Wrel = (const float*)d_in[3];
    const float* brel = (const float*)d_in[4];
    const float* Wroot = (const float*)d_in[5];
    const float* W1 = (const float*)d_in[6];
    const float* b1 = (const float*)d_in[7];
    const float* W2 = (const float*)d_in[8];
    const float* b2 = (const float*)d_in[9];
    float* out = (float*)d_out;

    cudaFuncSetAttribute(k_gemm_mma, cudaFuncAttributeMaxDynamicSharedMemorySize,
                         SM_TOTAL);

    uint32_t *xs, *h1, *h2;
    __half* wfp;
    cudaGetSymbolAddress((void**)&xs, g_xs);
    cudaGetSymbolAddress((void**)&h1, g_h1);
    cudaGetSymbolAddress((void**)&h2, g_h2);
    cudaGetSymbolAddress((void**)&wfp, g_Wf16);

    const int edge_blocks = (N_EDGES + 255) / 256;
    const int gather_blocks = (N_NODES + 15) / 16;   // 2 nodes per warp
    const int pool_blocks = (N_NODES + 8 * NODES_PER_WARP - 1) / (8 * NODES_PER_WARP);

    // Setup (zero + x-convert + pad-zero + weight prep), then adjacency
    k_setup<<<SETUP_BLOCKS + 6, 256>>>(x, Wrel, Wroot);
    k_fill<<<edge_blocks, 256>>>(ei);

    // Layer 0: xs -> h1
    k_gather<<<gather_blocks, 256>>>(xs);
    k_gemm_mma<<<GRID_GEMM, GT, SM_TOTAL>>>(xs, wfp + 0 * 2 * IMG, brel, h1);
    // Layer 1: h1 -> h2
    k_gather<<<gather_blocks, 256>>>(h1);
    k_gemm_mma<<<GRID_GEMM, GT, SM_TOTAL>>>(h1, wfp + 1 * 2 * IMG, brel + D, h2);
    // Layer 2: h2 -> h1
    k_gather<<<gather_blocks, 256>>>(h2);
    k_gemm_mma<<<GRID_GEMM, GT, SM_TOTAL>>>(h2, wfp + 2 * 2 * IMG, brel + 2 * D, h1);

    // Pool + head
    k_pool<<<pool_blocks, 256>>>(h1, batch);
    k_head<<<N_GRAPHS, 128>>>(W1, b1, W2, b2, out);
}